// round 16
// baseline (speedup 1.0000x reference)
#include <cuda_runtime.h>

#define NN 8192
#define FF 128
#define EE 262144
#define METAL 64
#define NOUT 17
#define TWO_N (2*NN)
#define TWO_E (2*EE)
#define KSPLIT 128
#define KCHUNK (TWO_N / KSPLIT)   // 128
#define TPB 256

// edge roles: 4 edges per thread, 512 blocks (measured best)
#define QQ (EE / 4)                  // 65536
#define EDGE_BLOCKS ((2 * QQ) / TPB) // 512
#define SELF_BLOCKS (TWO_N / TPB)    // 64
#define V_BLOCKS (TWO_N / 8)         // 2048 (warp per node, 8 warps/block)
#define GEMV_WORKERS (4 * KSPLIT)    // 512
#define OUT_BLOCKS (NN / TPB)        // 32

// Wi L2-prefetch: self-role slack of scat<2>/scat<3> ONLY; 26 lines/thread
// = 54.5MB/round, 109MB total (fits L2 once, fetched last). Proven config.
#define PF_PER 26
#define PF_REGION ((size_t)TWO_N * PF_PER * 128)

// ---- scratch (device globals: no allocation allowed) ----
__device__ int      d_degi[TWO_N];   // zero at entry; reset by init role each replay
__device__ float    d_v[TWO_N];      // x @ wc
__device__ float4   d_sv[5][TWO_N];  // per-round {au, aw, dv, 0}
__device__ float    d_res[NN];       // zero at entry; reset by out role each replay
__device__ float    d_c[4];          // c1, c2, c3, c4
__device__ unsigned c_init_done;     // reset by head each replay
__device__ unsigned c_gemv_done;     // reset by head each replay

__device__ __forceinline__ void redv2(float4* p, float a, float b) {
    asm volatile("red.global.add.v2.f32 [%0], {%1, %2};"
                 :: "l"(p), "f"(a), "f"(b) : "memory");
}
__device__ __forceinline__ void pf_l2(const void* p) {
    asm volatile("prefetch.global.L2 [%0];" :: "l"(p));
}
__device__ __forceinline__ void spin_until(unsigned* ctr, unsigned target) {
    if (threadIdx.x == 0) {
        while (*(volatile unsigned*)ctr != target) __nanosleep(32);
    }
    __syncthreads();
    __threadfence();
}

// compute combined 128-vector wc into smem (thread f < 128)
__device__ __forceinline__ void build_wc(float* swc,
                                         const float* __restrict__ W1,
                                         const float* __restrict__ W2,
                                         const float* __restrict__ W3,
                                         const float* __restrict__ W4) {
    if (threadIdx.x < FF) {
        int f = threadIdx.x;
        float w34[4], w234[8];
#pragma unroll
        for (int c = 0; c < 4; c++)
            w34[c] = W3[c * 2 + 0] * W4[0] + W3[c * 2 + 1] * W4[1];
#pragma unroll
        for (int r = 0; r < 8; r++) {
            float s = 0.0f;
#pragma unroll
            for (int c = 0; c < 4; c++) s += W2[r * 4 + c] * w34[c];
            w234[r] = s;
        }
        float s = 0.0f;
#pragma unroll
        for (int r = 0; r < 8; r++) s += W1[f * 8 + r] * w234[r];
        swc[f] = s;
    }
    __syncthreads();
}

// ====== head: degree count || v = x@wc || c-consts+counter reset || out init ======
__global__ void k_head(const int* __restrict__ ei1, const int* __restrict__ ei2,
                       const float* __restrict__ x1, const float* __restrict__ x2,
                       const float* __restrict__ W1, const float* __restrict__ b1,
                       const float* __restrict__ W2, const float* __restrict__ b2,
                       const float* __restrict__ W3, const float* __restrict__ b3,
                       const float* __restrict__ W4, const float* __restrict__ b4,
                       const float* __restrict__ meta, const float* __restrict__ Wf,
                       const float* __restrict__ bf, float* __restrict__ out) {
    __shared__ float swc[FF];
    int b = blockIdx.x;
    if (b < EDGE_BLOCKS) {
        int t = b * TPB + threadIdx.x;
        int4 a; int off;
        if (t < QQ) { a = ((const int4*)(ei1 + EE))[t];      off = 0;  }
        else        { a = ((const int4*)(ei2 + EE))[t - QQ]; off = NN; }
        atomicAdd(&d_degi[off + a.x], 1);
        atomicAdd(&d_degi[off + a.y], 1);
        atomicAdd(&d_degi[off + a.z], 1);
        atomicAdd(&d_degi[off + a.w], 1);
    } else if (b < EDGE_BLOCKS + V_BLOCKS) {
        build_wc(swc, W1, W2, W3, W4);
        int vb = b - EDGE_BLOCKS;
        int wid = threadIdx.x >> 5, lane = threadIdx.x & 31;
        int i = vb * 8 + wid;
        const float* x = (i < NN) ? (x1 + (size_t)i * FF)
                                  : (x2 + (size_t)(i - NN) * FF);
        float4 v = ((const float4*)x)[lane];
        float4 w = ((const float4*)swc)[lane];
        float s = v.x * w.x + v.y * w.y + v.z * w.z + v.w * w.w;
#pragma unroll
        for (int o = 16; o > 0; o >>= 1) s += __shfl_xor_sync(0xffffffff, s, o);
        if (lane == 0) d_v[i] = s;
    } else if (b == EDGE_BLOCKS + V_BLOCKS) {
        if (threadIdx.x == 0) {
            c_init_done = 0;                 // reset role counters for this replay
            c_gemv_done = 0;
            float w34[4], w234[8];
#pragma unroll
            for (int c = 0; c < 4; c++)
                w34[c] = W3[c * 2 + 0] * W4[0] + W3[c * 2 + 1] * W4[1];
#pragma unroll
            for (int r = 0; r < 8; r++) {
                float s = 0.0f;
#pragma unroll
                for (int c = 0; c < 4; c++) s += W2[r * 4 + c] * w34[c];
                w234[r] = s;
            }
            float c1 = 0.0f, c2 = 0.0f;
#pragma unroll
            for (int r = 0; r < 8; r++) c1 += b1[r] * w234[r];
#pragma unroll
            for (int c = 0; c < 4; c++) c2 += b2[c] * w34[c];
            d_c[0] = c1;
            d_c[1] = c2;
            d_c[2] = b3[0] * W4[0] + b3[1] * W4[1];
            d_c[3] = b4[0];
        }
    } else {
        if (threadIdx.x < NOUT) {
            int j = threadIdx.x;
            float s = bf[j];
#pragma unroll 8
            for (int m = 0; m < METAL; m++)
                s += meta[m] * Wf[(size_t)(NN + m) * NOUT + j];
            out[j] = s;
        }
    }
}

// ---- scatter round R ----
// R==0: 512 edge blocks (spin on init) + 64 init-role blocks. Self-loop for
//       round 0 is pre-seeded into sv[1] by the init role (no self blocks).
// R>0:  512 edge blocks + 64 self blocks (PF Wi regions 0,1 in rounds 2,3).
// All blocks co-resident, so spin ordering is deadlock-free.
template <int R>
__global__ void k_scat(const int* __restrict__ ei1, const int* __restrict__ ei2,
                       const float* __restrict__ Wi) {
    const float4* S = d_sv[R];
    float4*       D = d_sv[R + 1];
    int b = blockIdx.x;
    if (b < EDGE_BLOCKS) {
        // -------- edge role --------
        int t = b * TPB + threadIdx.x;
        int4 s4, d4; int off;
        if (t < QQ) {
            s4 = ((const int4*)ei1)[t];       d4 = ((const int4*)(ei1 + EE))[t];       off = 0;
        } else {
            s4 = ((const int4*)ei2)[t - QQ];  d4 = ((const int4*)(ei2 + EE))[t - QQ];  off = NN;
        }
        if (R == 0) spin_until(&c_init_done, SELF_BLOCKS);   // wait for struct init
        float4 p0 = S[off + s4.x];
        float4 p1 = S[off + s4.y];
        float4 p2 = S[off + s4.z];
        float4 p3 = S[off + s4.w];
        float a0, b0, a1, b1, a2, b2, a3, b3;
        if (R == 0) {
            a0 = p0.x; b0 = p0.y; a1 = p1.x; b1 = p1.y;
            a2 = p2.x; b2 = p2.y; a3 = p3.x; b3 = p3.y;
        } else {
            float z0 = p0.z * p0.z, z1 = p1.z * p1.z, z2 = p2.z * p2.z, z3 = p3.z * p3.z;
            a0 = z0 * p0.x; b0 = z0 * p0.y;
            a1 = z1 * p1.x; b1 = z1 * p1.y;
            a2 = z2 * p2.x; b2 = z2 * p2.y;
            a3 = z3 * p3.x; b3 = z3 * p3.y;
        }
        redv2(&D[off + d4.x], a0, b0);
        redv2(&D[off + d4.y], a1, b1);
        redv2(&D[off + d4.z], a2, b2);
        redv2(&D[off + d4.w], a3, b3);
    } else {
        int i = (b - EDGE_BLOCKS) * TPB + threadIdx.x;
        if (R == 0) {
            // -------- init role: build structs, seed sv[1] with self z0 --------
            int dg = d_degi[i];
            d_degi[i] = 0;                             // reset for next replay
            float dv = rsqrtf((float)(dg + 1));
            float g = dv * d_v[i];
            d_sv[0][i] = make_float4(g, dv, dv, 0.0f);
            d_sv[1][i] = make_float4(g, dv, dv, 0.0f); // zero + self-loop z0
#pragma unroll
            for (int r = 2; r <= 4; r++)
                d_sv[r][i] = make_float4(0.0f, 0.0f, dv, 0.0f);
            __threadfence();
            __syncthreads();
            if (threadIdx.x == 0) atomicAdd(&c_init_done, 1);
        } else {
            // -------- self-loop role (+PF in rounds 2,3) --------
            float4 p = S[i];
            float z = p.z * p.z;
            redv2(&D[i], z * p.x, z * p.y);
            if (R >= 2) {
                const char* base = (const char*)Wi + (size_t)(R - 2) * PF_REGION;
#pragma unroll
                for (int q = 0; q < PF_PER; q++)
                    pf_l2(base + ((size_t)q * TWO_N + i) * 128);
            }
        }
    }
}

// ---- gemv: 512 worker blocks (y < KSPLIT) + 32 out-role blocks, spin-ordered ----
__global__ void __launch_bounds__(TPB) k_wi_gemv(
    const float* __restrict__ Wi, const float* __restrict__ Wf,
    const float* __restrict__ bi, float* __restrict__ out) {
    if (blockIdx.y < KSPLIT) {
        // -------- worker role (exact R12 inner loop) --------
        __shared__ float sh[KCHUNK];
        int k0 = blockIdx.y * KCHUNK;
        if (threadIdx.x < KCHUNK) {
            int k = k0 + threadIdx.x;
            float4 q1 = d_sv[1][k];
            float4 q2 = d_sv[2][k];
            float4 q3 = d_sv[3][k];
            float4 q4 = d_sv[4][k];
            float dv = q4.z;
            sh[threadIdx.x] = dv * (q4.x + d_c[0] * q3.y + d_c[1] * q2.y
                                    + d_c[2] * q1.y) + d_c[3];
        }
        __syncthreads();
        int j4a = blockIdx.x * TPB + threadIdx.x;     // 0..1023
        int j4b = j4a + 1024;
        const float4* Wi4 = (const float4*)Wi;
        float4 acc0 = make_float4(0.f, 0.f, 0.f, 0.f);
        float4 acc1 = make_float4(0.f, 0.f, 0.f, 0.f);
#pragma unroll 4
        for (int kk = 0; kk < KCHUNK; kk++) {
            float c = sh[kk];
            size_t row = (size_t)(k0 + kk) * (NN / 4);
            float4 w0 = __ldcs(&Wi4[row + j4a]);
            float4 w1 = __ldcs(&Wi4[row + j4b]);
            acc0.x += c * w0.x; acc0.y += c * w0.y; acc0.z += c * w0.z; acc0.w += c * w0.w;
            acc1.x += c * w1.x; acc1.y += c * w1.y; acc1.z += c * w1.z; acc1.w += c * w1.w;
        }
        int ja = j4a * 4, jb = j4b * 4;
        atomicAdd(&d_res[ja + 0], acc0.x);
        atomicAdd(&d_res[ja + 1], acc0.y);
        atomicAdd(&d_res[ja + 2], acc0.z);
        atomicAdd(&d_res[ja + 3], acc0.w);
        atomicAdd(&d_res[jb + 0], acc1.x);
        atomicAdd(&d_res[jb + 1], acc1.y);
        atomicAdd(&d_res[jb + 2], acc1.z);
        atomicAdd(&d_res[jb + 3], acc1.w);
        __threadfence();
        __syncthreads();
        if (threadIdx.x == 0) atomicAdd(&c_gemv_done, 1);
    } else {
        // -------- out role: out += (res + bi) @ Wf[:N] --------
        int obid = (blockIdx.y - KSPLIT) * gridDim.x + blockIdx.x;   // 0..31
        int i = obid * TPB + threadIdx.x;
        float bv = bi[i];                         // preload (inputs, hazard-free)
        float wrow[NOUT];
#pragma unroll
        for (int j = 0; j < NOUT; j++) wrow[j] = Wf[(size_t)i * NOUT + j];
        spin_until(&c_gemv_done, GEMV_WORKERS);
        float r = d_res[i] + bv;
        d_res[i] = 0.0f;                          // reset for next replay
        float acc[NOUT];
#pragma unroll
        for (int j = 0; j < NOUT; j++) acc[j] = r * wrow[j];
#pragma unroll
        for (int j = 0; j < NOUT; j++) {
#pragma unroll
            for (int o = 16; o > 0; o >>= 1)
                acc[j] += __shfl_xor_sync(0xffffffff, acc[j], o);
        }
        if ((threadIdx.x & 31) == 0) {
#pragma unroll
            for (int j = 0; j < NOUT; j++) atomicAdd(&out[j], acc[j]);
        }
    }
}

// ================================================================= launch
extern "C" void kernel_launch(void* const* d_in, const int* in_sizes, int n_in,
                              void* d_out, int out_size) {
    const float* x1   = (const float*)d_in[0];
    const float* x2   = (const float*)d_in[1];
    const float* meta = (const float*)d_in[2];
    const float* W1   = (const float*)d_in[3];
    const float* b1   = (const float*)d_in[4];
    const float* W2   = (const float*)d_in[5];
    const float* b2   = (const float*)d_in[6];
    const float* W3   = (const float*)d_in[7];
    const float* b3   = (const float*)d_in[8];
    const float* W4   = (const float*)d_in[9];
    const float* b4   = (const float*)d_in[10];
    const float* Wi   = (const float*)d_in[11];
    const float* bi   = (const float*)d_in[12];
    const float* Wf   = (const float*)d_in[13];
    const float* bf   = (const float*)d_in[14];
    const int*   ei1  = (const int*)d_in[15];
    const int*   ei2  = (const int*)d_in[16];
    float* out = (float*)d_out;

    k_head<<<EDGE_BLOCKS + V_BLOCKS + 2, TPB>>>(ei1, ei2, x1, x2, W1, b1, W2, b2,
                                                W3, b3, W4, b4, meta, Wf, bf, out);
    k_scat<0><<<EDGE_BLOCKS + SELF_BLOCKS, TPB>>>(ei1, ei2, Wi);   // init role inside
    k_scat<1><<<EDGE_BLOCKS + SELF_BLOCKS, TPB>>>(ei1, ei2, Wi);
    k_scat<2><<<EDGE_BLOCKS + SELF_BLOCKS, TPB>>>(ei1, ei2, Wi);
    k_scat<3><<<EDGE_BLOCKS + SELF_BLOCKS, TPB>>>(ei1, ei2, Wi);
    {
        dim3 grid(4, KSPLIT + OUT_BLOCKS / 4);   // (4, 136): 512 workers + 32 out
        k_wi_gemv<<<grid, TPB>>>(Wi, Wf, bi, out);
    }
}

// round 17
// speedup vs baseline: 1.0417x; 1.0417x over previous
#include <cuda_runtime.h>

#define NN 8192
#define FF 128
#define EE 262144
#define METAL 64
#define NOUT 17
#define TWO_N (2*NN)
#define TWO_E (2*EE)
#define KSPLIT 128
#define KCHUNK (TWO_N / KSPLIT)   // 128
#define TPB 256

// edge roles: 4 edges per thread, 512 blocks (measured best)
#define QQ (EE / 4)                  // 65536
#define EDGE_BLOCKS ((2 * QQ) / TPB) // 512
#define SELF_BLOCKS (TWO_N / TPB)    // 64
#define V_BLOCKS (TWO_N / 8)         // 2048 (warp per node, 8 warps/block)

// Wi L2-prefetch: 13 lines/thread/round = 27.25MB/round x 4 rounds = 109MB
// total (same warm footprint as the proven config, but each round's PF now
// fits inside the ~8.7us edge-role shadow instead of extending rounds 2,3).
#define PF_PER 13
#define PF_REGION ((size_t)TWO_N * PF_PER * 128)   // 27.25MB per round

// ---- scratch (device globals: no allocation allowed) ----
__device__ int    d_degi[TWO_N];     // zero at entry; reset by k_init each replay
__device__ float  d_v[TWO_N];        // x @ wc
__device__ float4 d_sv[5][TWO_N];    // per-round {au, aw, dv, 0}
__device__ float  d_res[NN];         // zero at entry; reset by k_out_acc each replay
__device__ float  d_c[4];            // c1, c2, c3, c4

__device__ __forceinline__ void redv2(float4* p, float a, float b) {
    asm volatile("red.global.add.v2.f32 [%0], {%1, %2};"
                 :: "l"(p), "f"(a), "f"(b) : "memory");
}
__device__ __forceinline__ void pf_l2(const void* p) {
    asm volatile("prefetch.global.L2 [%0];" :: "l"(p));
}

// compute combined 128-vector wc into smem (thread f < 128)
__device__ __forceinline__ void build_wc(float* swc,
                                         const float* __restrict__ W1,
                                         const float* __restrict__ W2,
                                         const float* __restrict__ W3,
                                         const float* __restrict__ W4) {
    if (threadIdx.x < FF) {
        int f = threadIdx.x;
        float w34[4], w234[8];
#pragma unroll
        for (int c = 0; c < 4; c++)
            w34[c] = W3[c * 2 + 0] * W4[0] + W3[c * 2 + 1] * W4[1];
#pragma unroll
        for (int r = 0; r < 8; r++) {
            float s = 0.0f;
#pragma unroll
            for (int c = 0; c < 4; c++) s += W2[r * 4 + c] * w34[c];
            w234[r] = s;
        }
        float s = 0.0f;
#pragma unroll
        for (int r = 0; r < 8; r++) s += W1[f * 8 + r] * w234[r];
        swc[f] = s;
    }
    __syncthreads();
}

// ====== head: degree count || v = x@wc || c-constants || out init (role blocks) ======
__global__ void k_head(const int* __restrict__ ei1, const int* __restrict__ ei2,
                       const float* __restrict__ x1, const float* __restrict__ x2,
                       const float* __restrict__ W1, const float* __restrict__ b1,
                       const float* __restrict__ W2, const float* __restrict__ b2,
                       const float* __restrict__ W3, const float* __restrict__ b3,
                       const float* __restrict__ W4, const float* __restrict__ b4,
                       const float* __restrict__ meta, const float* __restrict__ Wf,
                       const float* __restrict__ bf, float* __restrict__ out) {
    __shared__ float swc[FF];
    int b = blockIdx.x;
    if (b < EDGE_BLOCKS) {
        int t = b * TPB + threadIdx.x;
        int4 a; int off;
        if (t < QQ) { a = ((const int4*)(ei1 + EE))[t];      off = 0;  }
        else        { a = ((const int4*)(ei2 + EE))[t - QQ]; off = NN; }
        atomicAdd(&d_degi[off + a.x], 1);
        atomicAdd(&d_degi[off + a.y], 1);
        atomicAdd(&d_degi[off + a.z], 1);
        atomicAdd(&d_degi[off + a.w], 1);
    } else if (b < EDGE_BLOCKS + V_BLOCKS) {
        build_wc(swc, W1, W2, W3, W4);
        int vb = b - EDGE_BLOCKS;
        int wid = threadIdx.x >> 5, lane = threadIdx.x & 31;
        int i = vb * 8 + wid;
        const float* x = (i < NN) ? (x1 + (size_t)i * FF)
                                  : (x2 + (size_t)(i - NN) * FF);
        float4 v = ((const float4*)x)[lane];
        float4 w = ((const float4*)swc)[lane];
        float s = v.x * w.x + v.y * w.y + v.z * w.z + v.w * w.w;
#pragma unroll
        for (int o = 16; o > 0; o >>= 1) s += __shfl_xor_sync(0xffffffff, s, o);
        if (lane == 0) d_v[i] = s;
    } else if (b == EDGE_BLOCKS + V_BLOCKS) {
        if (threadIdx.x == 0) {
            float w34[4], w234[8];
#pragma unroll
            for (int c = 0; c < 4; c++)
                w34[c] = W3[c * 2 + 0] * W4[0] + W3[c * 2 + 1] * W4[1];
#pragma unroll
            for (int r = 0; r < 8; r++) {
                float s = 0.0f;
#pragma unroll
                for (int c = 0; c < 4; c++) s += W2[r * 4 + c] * w34[c];
                w234[r] = s;
            }
            float c1 = 0.0f, c2 = 0.0f;
#pragma unroll
            for (int r = 0; r < 8; r++) c1 += b1[r] * w234[r];
#pragma unroll
            for (int c = 0; c < 4; c++) c2 += b2[c] * w34[c];
            d_c[0] = c1;
            d_c[1] = c2;
            d_c[2] = b3[0] * W4[0] + b3[1] * W4[1];
            d_c[3] = b4[0];
        }
    } else {
        if (threadIdx.x < NOUT) {
            int j = threadIdx.x;
            float s = bf[j];
#pragma unroll 8
            for (int m = 0; m < METAL; m++)
                s += meta[m] * Wf[(size_t)(NN + m) * NOUT + j];
            out[j] = s;
        }
    }
}

// ---- init: dv = rsqrt(deg+1); build structs; reset degi ----
__global__ void k_init() {
    int i = blockIdx.x * blockDim.x + threadIdx.x;
    if (i >= TWO_N) return;
    int dg = d_degi[i];
    d_degi[i] = 0;                                // reset for next replay
    float dv = rsqrtf((float)(dg + 1));
    float v = d_v[i];
    d_sv[0][i] = make_float4(dv * v, dv, dv, 0.0f);
#pragma unroll
    for (int r = 1; r <= 4; r++)
        d_sv[r][i] = make_float4(0.0f, 0.0f, dv, 0.0f);
}

// ---- scatter round R: edge blocks + self blocks (PF region R in every round) ----
template <int R>
__global__ void k_scat(const int* __restrict__ ei1, const int* __restrict__ ei2,
                       const float* __restrict__ Wi) {
    const float4* S = d_sv[R];
    float4*       D = d_sv[R + 1];
    int b = blockIdx.x;
    if (b < EDGE_BLOCKS) {
        int t = b * TPB + threadIdx.x;
        int4 s4, d4; int off;
        if (t < QQ) {
            s4 = ((const int4*)ei1)[t];       d4 = ((const int4*)(ei1 + EE))[t];       off = 0;
        } else {
            s4 = ((const int4*)ei2)[t - QQ];  d4 = ((const int4*)(ei2 + EE))[t - QQ];  off = NN;
        }
        float4 p0 = S[off + s4.x];
        float4 p1 = S[off + s4.y];
        float4 p2 = S[off + s4.z];
        float4 p3 = S[off + s4.w];
        float a0, b0, a1, b1, a2, b2, a3, b3;
        if (R == 0) {
            a0 = p0.x; b0 = p0.y; a1 = p1.x; b1 = p1.y;
            a2 = p2.x; b2 = p2.y; a3 = p3.x; b3 = p3.y;
        } else {
            float z0 = p0.z * p0.z, z1 = p1.z * p1.z, z2 = p2.z * p2.z, z3 = p3.z * p3.z;
            a0 = z0 * p0.x; b0 = z0 * p0.y;
            a1 = z1 * p1.x; b1 = z1 * p1.y;
            a2 = z2 * p2.x; b2 = z2 * p2.y;
            a3 = z3 * p3.x; b3 = z3 * p3.y;
        }
        redv2(&D[off + d4.x], a0, b0);
        redv2(&D[off + d4.y], a1, b1);
        redv2(&D[off + d4.z], a2, b2);
        redv2(&D[off + d4.w], a3, b3);
    } else {
        // self-loop role: RED + 27.25MB PF of Wi region R (hidden in edge shadow)
        int i = (b - EDGE_BLOCKS) * TPB + threadIdx.x;
        float4 p = S[i];
        float a, bb;
        if (R == 0) { a = p.x; bb = p.y; }
        else        { float z = p.z * p.z; a = z * p.x; bb = z * p.y; }
        redv2(&D[i], a, bb);
        const char* base = (const char*)Wi + (size_t)R * PF_REGION;
#pragma unroll
        for (int q = 0; q < PF_PER; q++)
            pf_l2(base + ((size_t)q * TWO_N + i) * 128);
    }
}

// ---- big GEMV (2 float4/thread ILP): res[j] += sum_k h[k]*Wi[k*N+j]
__global__ void __launch_bounds__(TPB) k_wi_gemv(const float* __restrict__ Wi) {
    __shared__ float sh[KCHUNK];
    int k0 = blockIdx.y * KCHUNK;
    if (threadIdx.x < KCHUNK) {
        int k = k0 + threadIdx.x;
        float4 q1 = d_sv[1][k];
        float4 q2 = d_sv[2][k];
        float4 q3 = d_sv[3][k];
        float4 q4 = d_sv[4][k];
        float dv = q4.z;
        sh[threadIdx.x] = dv * (q4.x + d_c[0] * q3.y + d_c[1] * q2.y + d_c[2] * q1.y)
                          + d_c[3];
    }
    __syncthreads();
    int j4a = blockIdx.x * TPB + threadIdx.x;     // 0..1023
    int j4b = j4a + 1024;
    const float4* Wi4 = (const float4*)Wi;
    float4 acc0 = make_float4(0.f, 0.f, 0.f, 0.f);
    float4 acc1 = make_float4(0.f, 0.f, 0.f, 0.f);
#pragma unroll 4
    for (int kk = 0; kk < KCHUNK; kk++) {
        float c = sh[kk];
        size_t row = (size_t)(k0 + kk) * (NN / 4);
        float4 w0 = __ldcs(&Wi4[row + j4a]);
        float4 w1 = __ldcs(&Wi4[row + j4b]);
        acc0.x += c * w0.x; acc0.y += c * w0.y; acc0.z += c * w0.z; acc0.w += c * w0.w;
        acc1.x += c * w1.x; acc1.y += c * w1.y; acc1.z += c * w1.z; acc1.w += c * w1.w;
    }
    int ja = j4a * 4, jb = j4b * 4;
    atomicAdd(&d_res[ja + 0], acc0.x);
    atomicAdd(&d_res[ja + 1], acc0.y);
    atomicAdd(&d_res[ja + 2], acc0.z);
    atomicAdd(&d_res[ja + 3], acc0.w);
    atomicAdd(&d_res[jb + 0], acc1.x);
    atomicAdd(&d_res[jb + 1], acc1.y);
    atomicAdd(&d_res[jb + 2], acc1.z);
    atomicAdd(&d_res[jb + 3], acc1.w);
}

// ---------------- out += (res + bi) @ Wf[:N]; reset res for next replay
__global__ void k_out_acc(const float* __restrict__ Wf,
                          const float* __restrict__ bi,
                          float* __restrict__ out) {
    int i = blockIdx.x * blockDim.x + threadIdx.x;   // exactly NN threads
    float r = d_res[i] + bi[i];
    d_res[i] = 0.0f;                                  // reset for next replay
    float acc[NOUT];
#pragma unroll
    for (int j = 0; j < NOUT; j++) acc[j] = r * Wf[(size_t)i * NOUT + j];
#pragma unroll
    for (int j = 0; j < NOUT; j++) {
#pragma unroll
        for (int o = 16; o > 0; o >>= 1)
            acc[j] += __shfl_xor_sync(0xffffffff, acc[j], o);
    }
    if ((threadIdx.x & 31) == 0) {
#pragma unroll
        for (int j = 0; j < NOUT; j++) atomicAdd(&out[j], acc[j]);
    }
}

// ================================================================= launch
extern "C" void kernel_launch(void* const* d_in, const int* in_sizes, int n_in,
                              void* d_out, int out_size) {
    const float* x1   = (const float*)d_in[0];
    const float* x2   = (const float*)d_in[1];
    const float* meta = (const float*)d_in[2];
    const float* W1   = (const float*)d_in[3];
    const float* b1   = (const float*)d_in[4];
    const float* W2   = (const float*)d_in[5];
    const float* b2   = (const float*)d_in[6];
    const float* W3   = (const float*)d_in[7];
    const float* b3   = (const float*)d_in[8];
    const float* W4   = (const float*)d_in[9];
    const float* b4   = (const float*)d_in[10];
    const float* Wi   = (const float*)d_in[11];
    const float* bi   = (const float*)d_in[12];
    const float* Wf   = (const float*)d_in[13];
    const float* bf   = (const float*)d_in[14];
    const int*   ei1  = (const int*)d_in[15];
    const int*   ei2  = (const int*)d_in[16];
    float* out = (float*)d_out;

    k_head<<<EDGE_BLOCKS + V_BLOCKS + 2, TPB>>>(ei1, ei2, x1, x2, W1, b1, W2, b2,
                                                W3, b3, W4, b4, meta, Wf, bf, out);
    k_init<<<TWO_N / TPB, TPB>>>();
    k_scat<0><<<EDGE_BLOCKS + SELF_BLOCKS, TPB>>>(ei1, ei2, Wi);
    k_scat<1><<<EDGE_BLOCKS + SELF_BLOCKS, TPB>>>(ei1, ei2, Wi);
    k_scat<2><<<EDGE_BLOCKS + SELF_BLOCKS, TPB>>>(ei1, ei2, Wi);
    k_scat<3><<<EDGE_BLOCKS + SELF_BLOCKS, TPB>>>(ei1, ei2, Wi);
    {
        dim3 grid(NN / (TPB * 8), KSPLIT);   // (4, 128) = 512 blocks
        k_wi_gemv<<<grid, TPB>>>(Wi);
    }
    k_out_acc<<<NN / TPB, TPB>>>(Wf, bi, out);
}